// round 2
// baseline (speedup 1.0000x reference)
#include <cuda_runtime.h>
#include <cstdint>

#define NUM_LEVELS 16
#define BASE_RES   16
#define TABLE_MASK ((1u << 19) - 1u)
#define TABLE_FLOATS (1u << 20)   // 2^19 entries * 2 floats
#define P1 2654435761u
#define P2 805459861u

__global__ __launch_bounds__(256)
void hash_encode_kernel(const float* __restrict__ x,
                        const float* __restrict__ tables,
                        float* __restrict__ out,
                        int N)
{
    int gid = blockIdx.x * blockDim.x + threadIdx.x;
    int n = gid >> 4;          // point index
    if (n >= N) return;
    int l = gid & 15;          // level index (level-major in warp -> coalesced stores)

    // Load point (broadcast across the 16 lanes of the same point)
    float px = __ldg(x + 3 * n + 0);
    float py = __ldg(x + 3 * n + 1);
    float pz = __ldg(x + 3 * n + 2);

    // normalize: clip((x + 1)/2, 0, 1 - 1e-6)  [fp32, matching jnp exactly]
    const float HI = 0.999999f;  // float32(1.0 - 1e-6)
    float xn = fminf(fmaxf((px + 1.0f) * 0.5f, 0.0f), HI);
    float yn = fminf(fmaxf((py + 1.0f) * 0.5f, 0.0f), HI);
    float zn = fminf(fmaxf((pz + 1.0f) * 0.5f, 0.0f), HI);

    float res = (float)(BASE_RES << l);

    float sx = xn * res, sy = yn * res, sz = zn * res;
    float fx0 = floorf(sx), fy0 = floorf(sy), fz0 = floorf(sz);
    float fx = sx - fx0, fy = sy - fy0, fz = sz - fz0;

    uint32_t cx = (uint32_t)(int)fx0;
    uint32_t cy = (uint32_t)(int)fy0;
    uint32_t cz = (uint32_t)(int)fz0;

    // hash terms; (c+1)*P == c*P + P under uint32 wraparound
    uint32_t hx0 = cx;                 // * PRIMES[0] = 1
    uint32_t hx1 = cx + 1u;
    uint32_t hy0 = cy * P1;
    uint32_t hy1 = hy0 + P1;
    uint32_t hz0 = (cz * P2) ^ (uint32_t)l;   // fold level XOR into z term
    uint32_t hz1 = ((cz * P2) + P2) ^ (uint32_t)l;

    const float2* __restrict__ tbl =
        (const float2*)(tables) + ((size_t)l << 19);

    // 8 corners: k = dx*4 + dy*2 + dz  (matches OFFSETS ordering; sum order-free)
    float2 e[8];
    float  w[8];
    float wx1 = fx, wx0 = 1.0f - fx;
    float wy1 = fy, wy0 = 1.0f - fy;
    float wz1 = fz, wz0 = 1.0f - fz;

#pragma unroll
    for (int k = 0; k < 8; ++k) {
        uint32_t h = ((k & 4) ? hx1 : hx0)
                   ^ ((k & 2) ? hy1 : hy0)
                   ^ ((k & 1) ? hz1 : hz0);
        uint32_t idx = h & TABLE_MASK;
        e[k] = __ldg(tbl + idx);        // 8 independent gathers -> MLP=8
        w[k] = ((k & 4) ? wx1 : wx0)
             * ((k & 2) ? wy1 : wy0)
             * ((k & 1) ? wz1 : wz0);
    }

    float a0 = 0.0f, a1 = 0.0f;
#pragma unroll
    for (int k = 0; k < 8; ++k) {
        a0 = fmaf(w[k], e[k].x, a0);
        a1 = fmaf(w[k], e[k].y, a1);
    }

    // out[n, l*2 .. l*2+1]  -> warp stores 2 contiguous 128B rows
    float2* o = (float2*)(out + (size_t)n * (NUM_LEVELS * 2));
    o[l] = make_float2(a0, a1);
}

extern "C" void kernel_launch(void* const* d_in, const int* in_sizes, int n_in,
                              void* d_out, int out_size)
{
    const float* x      = (const float*)d_in[0];
    const float* tables = (const float*)d_in[1];
    float* out          = (float*)d_out;

    int N = in_sizes[0] / 3;
    int total = N * NUM_LEVELS;
    int block = 256;
    int grid = (total + block - 1) / block;
    hash_encode_kernel<<<grid, block>>>(x, tables, out, N);
}

// round 3
// speedup vs baseline: 1.0287x; 1.0287x over previous
#include <cuda_runtime.h>
#include <cstdint>

#define NUM_LEVELS 16
#define BASE_RES   16
#define TABLE_MASK ((1u << 19) - 1u)
#define P1 2654435761u
#define P2 805459861u

// Dense z-pair records for levels 0..2.
// Level l: R = 16<<l. Record grid: (R+1) x (R+1) x R  (x, y, z-pair index).
// record(x,y,z) = float4( v(x,y,z).x, v(x,y,z).y, v(x,y,z+1).x, v(x,y,z+1).y )
#define D0_SIZE (17 * 17 * 16)            // 4624
#define D1_SIZE (33 * 33 * 32)            // 34848
#define D2_SIZE (65 * 65 * 64)            // 270400
#define D1_BASE D0_SIZE                   // 4624
#define D2_BASE (D0_SIZE + D1_SIZE)       // 39472
#define D_TOTAL (D0_SIZE + D1_SIZE + D2_SIZE)  // 309872  (~4.96 MB)

__device__ float4 g_dense[D_TOTAL];

__global__ __launch_bounds__(256)
void build_dense_kernel(const float* __restrict__ tables)
{
    int t = blockIdx.x * blockDim.x + threadIdx.x;
    if (t >= D_TOTAL) return;

    int l, rem, R;
    if (t < D1_BASE)      { l = 0; rem = t;           R = 16; }
    else if (t < D2_BASE) { l = 1; rem = t - D1_BASE; R = 32; }
    else                  { l = 2; rem = t - D2_BASE; R = 64; }

    int z  = rem % R;
    int xy = rem / R;
    int y  = xy % (R + 1);
    int x  = xy / (R + 1);

    // hash = vx*1 ^ vy*P1 ^ vz*P2 ^ level   (uint32 wraparound)
    uint32_t hxy = (uint32_t)x ^ ((uint32_t)y * P1);
    uint32_t hz  = (uint32_t)z * P2;
    uint32_t i0 = (hxy ^ hz        ^ (uint32_t)l) & TABLE_MASK;
    uint32_t i1 = (hxy ^ (hz + P2) ^ (uint32_t)l) & TABLE_MASK;

    const float2* __restrict__ tbl = (const float2*)tables + ((size_t)l << 19);
    float2 e0 = __ldg(tbl + i0);
    float2 e1 = __ldg(tbl + i1);
    g_dense[t] = make_float4(e0.x, e0.y, e1.x, e1.y);
}

__global__ __launch_bounds__(256)
void hash_encode_kernel(const float* __restrict__ x,
                        const float* __restrict__ tables,
                        float* __restrict__ out,
                        int N)
{
    int gid = blockIdx.x * blockDim.x + threadIdx.x;
    int n = gid >> 4;          // point index
    if (n >= N) return;
    int l = gid & 15;          // level index (level-major -> coalesced stores)

    float px = __ldg(x + 3 * n + 0);
    float py = __ldg(x + 3 * n + 1);
    float pz = __ldg(x + 3 * n + 2);

    // clip((x + 1)/2, 0, 1 - 1e-6) in fp32, matching jnp
    const float HI = 0.999999f;
    float xn = fminf(fmaxf((px + 1.0f) * 0.5f, 0.0f), HI);
    float yn = fminf(fmaxf((py + 1.0f) * 0.5f, 0.0f), HI);
    float zn = fminf(fmaxf((pz + 1.0f) * 0.5f, 0.0f), HI);

    float res = (float)(BASE_RES << l);

    float sx = xn * res, sy = yn * res, sz = zn * res;
    float fx0 = floorf(sx), fy0 = floorf(sy), fz0 = floorf(sz);
    float fx = sx - fx0, fy = sy - fy0, fz = sz - fz0;

    int cx = (int)fx0, cy = (int)fy0, cz = (int)fz0;

    float wx1 = fx, wx0 = 1.0f - fx;
    float wy1 = fy, wy0 = 1.0f - fy;
    float wz1 = fz, wz0 = 1.0f - fz;

    float a0, a1;

    if (l < 3) {
        // ---- dense path: 4 aligned 16B loads (z-pairs) ----
        int R   = BASE_RES << l;
        int Rp1 = R + 1;
        int base = (l == 0) ? 0 : (l == 1) ? D1_BASE : D2_BASE;

        int r00 = base + (cx * Rp1 + cy) * R + cz;
        int r01 = r00 + R;            // y+1
        int r10 = r00 + Rp1 * R;      // x+1
        int r11 = r10 + R;            // x+1, y+1

        float4 q00 = __ldg(g_dense + r00);
        float4 q01 = __ldg(g_dense + r01);
        float4 q10 = __ldg(g_dense + r10);
        float4 q11 = __ldg(g_dense + r11);

        // accumulate in corner order k = dx*4 + dy*2 + dz (matches ref sum order)
        float w;
        w = wx0 * wy0 * wz0; a0 = w * q00.x;            a1 = w * q00.y;
        w = wx0 * wy0 * wz1; a0 = fmaf(w, q00.z, a0);   a1 = fmaf(w, q00.w, a1);
        w = wx0 * wy1 * wz0; a0 = fmaf(w, q01.x, a0);   a1 = fmaf(w, q01.y, a1);
        w = wx0 * wy1 * wz1; a0 = fmaf(w, q01.z, a0);   a1 = fmaf(w, q01.w, a1);
        w = wx1 * wy0 * wz0; a0 = fmaf(w, q10.x, a0);   a1 = fmaf(w, q10.y, a1);
        w = wx1 * wy0 * wz1; a0 = fmaf(w, q10.z, a0);   a1 = fmaf(w, q10.w, a1);
        w = wx1 * wy1 * wz0; a0 = fmaf(w, q11.x, a0);   a1 = fmaf(w, q11.y, a1);
        w = wx1 * wy1 * wz1; a0 = fmaf(w, q11.z, a0);   a1 = fmaf(w, q11.w, a1);
    } else {
        // ---- hashed path: 8 independent 8B gathers ----
        uint32_t hx0 = (uint32_t)cx;
        uint32_t hx1 = hx0 + 1u;
        uint32_t hy0 = (uint32_t)cy * P1;
        uint32_t hy1 = hy0 + P1;
        uint32_t hzb = (uint32_t)cz * P2;
        uint32_t hz0 = hzb        ^ (uint32_t)l;
        uint32_t hz1 = (hzb + P2) ^ (uint32_t)l;

        const float2* __restrict__ tbl = (const float2*)tables + ((size_t)l << 19);

        float2 e[8];
        float  w[8];
#pragma unroll
        for (int k = 0; k < 8; ++k) {
            uint32_t h = ((k & 4) ? hx1 : hx0)
                       ^ ((k & 2) ? hy1 : hy0)
                       ^ ((k & 1) ? hz1 : hz0);
            e[k] = __ldg(tbl + (h & TABLE_MASK));
            w[k] = ((k & 4) ? wx1 : wx0)
                 * ((k & 2) ? wy1 : wy0)
                 * ((k & 1) ? wz1 : wz0);
        }
        a0 = 0.0f; a1 = 0.0f;
#pragma unroll
        for (int k = 0; k < 8; ++k) {
            a0 = fmaf(w[k], e[k].x, a0);
            a1 = fmaf(w[k], e[k].y, a1);
        }
    }

    float2* o = (float2*)(out + (size_t)n * (NUM_LEVELS * 2));
    o[l] = make_float2(a0, a1);
}

extern "C" void kernel_launch(void* const* d_in, const int* in_sizes, int n_in,
                              void* d_out, int out_size)
{
    const float* x      = (const float*)d_in[0];
    const float* tables = (const float*)d_in[1];
    float* out          = (float*)d_out;

    int N = in_sizes[0] / 3;

    build_dense_kernel<<<(D_TOTAL + 255) / 256, 256>>>(tables);

    int total = N * NUM_LEVELS;
    hash_encode_kernel<<<(total + 255) / 256, 256>>>(x, tables, out, N);
}

// round 4
// speedup vs baseline: 1.1414x; 1.1095x over previous
#include <cuda_runtime.h>
#include <cstdint>

#define NUM_LEVELS 16
#define BASE_RES   16
#define TABLE_MASK ((1u << 19) - 1u)
#define P1 2654435761u
#define P2 805459861u

// Dense z-pair records for levels 0..2.
#define D0_SIZE (17 * 17 * 16)
#define D1_SIZE (33 * 33 * 32)
#define D2_SIZE (65 * 65 * 64)
#define D1_BASE D0_SIZE
#define D2_BASE (D0_SIZE + D1_SIZE)
#define D_TOTAL (D0_SIZE + D1_SIZE + D2_SIZE)   // 309872 (~4.96 MB)

__device__ float4 g_dense[D_TOTAL];

__global__ __launch_bounds__(256)
void build_dense_kernel(const float* __restrict__ tables)
{
    int t = blockIdx.x * blockDim.x + threadIdx.x;
    if (t >= D_TOTAL) return;

    int l, rem, R;
    if (t < D1_BASE)      { l = 0; rem = t;           R = 16; }
    else if (t < D2_BASE) { l = 1; rem = t - D1_BASE; R = 32; }
    else                  { l = 2; rem = t - D2_BASE; R = 64; }

    int z  = rem % R;
    int xy = rem / R;
    int y  = xy % (R + 1);
    int x  = xy / (R + 1);

    uint32_t hxy = (uint32_t)x ^ ((uint32_t)y * P1);
    uint32_t hz  = (uint32_t)z * P2;
    uint32_t i0 = (hxy ^ hz        ^ (uint32_t)l) & TABLE_MASK;
    uint32_t i1 = (hxy ^ (hz + P2) ^ (uint32_t)l) & TABLE_MASK;

    const float2* __restrict__ tbl = (const float2*)tables + ((size_t)l << 19);
    float2 e0 = __ldg(tbl + i0);
    float2 e1 = __ldg(tbl + i1);
    g_dense[t] = make_float4(e0.x, e0.y, e1.x, e1.y);
}

__global__ __launch_bounds__(256)
void hash_encode_kernel(const float* __restrict__ x,
                        const float* __restrict__ tables,
                        float* __restrict__ out,
                        int N)
{
    int gid = blockIdx.x * blockDim.x + threadIdx.x;
    int n = gid >> 4;
    if (n >= N) return;
    int l = gid & 15;

    float px = __ldg(x + 3 * n + 0);
    float py = __ldg(x + 3 * n + 1);
    float pz = __ldg(x + 3 * n + 2);

    const float HI = 0.999999f;
    float xn = fminf(fmaxf((px + 1.0f) * 0.5f, 0.0f), HI);
    float yn = fminf(fmaxf((py + 1.0f) * 0.5f, 0.0f), HI);
    float zn = fminf(fmaxf((pz + 1.0f) * 0.5f, 0.0f), HI);

    float res = (float)(BASE_RES << l);

    float sx = xn * res, sy = yn * res, sz = zn * res;
    float fx0 = floorf(sx), fy0 = floorf(sy), fz0 = floorf(sz);
    float fx = sx - fx0, fy = sy - fy0, fz = sz - fz0;

    int cx = (int)fx0, cy = (int)fy0, cz = (int)fz0;

    float wx1 = fx, wx0 = 1.0f - fx;
    float wy1 = fy, wy0 = 1.0f - fy;
    float wz1 = fz, wz0 = 1.0f - fz;

    float a0, a1;

    if (l < 3) {
        // ---- dense path: 4 aligned 16B z-pair loads ----
        int R   = BASE_RES << l;
        int Rp1 = R + 1;
        int base = (l == 0) ? 0 : (l == 1) ? D1_BASE : D2_BASE;

        int r00 = base + (cx * Rp1 + cy) * R + cz;
        int r01 = r00 + R;
        int r10 = r00 + Rp1 * R;
        int r11 = r10 + R;

        float4 q00 = __ldg(g_dense + r00);
        float4 q01 = __ldg(g_dense + r01);
        float4 q10 = __ldg(g_dense + r10);
        float4 q11 = __ldg(g_dense + r11);

        float w;
        w = wx0 * wy0 * wz0; a0 = w * q00.x;            a1 = w * q00.y;
        w = wx0 * wy0 * wz1; a0 = fmaf(w, q00.z, a0);   a1 = fmaf(w, q00.w, a1);
        w = wx0 * wy1 * wz0; a0 = fmaf(w, q01.x, a0);   a1 = fmaf(w, q01.y, a1);
        w = wx0 * wy1 * wz1; a0 = fmaf(w, q01.z, a0);   a1 = fmaf(w, q01.w, a1);
        w = wx1 * wy0 * wz0; a0 = fmaf(w, q10.x, a0);   a1 = fmaf(w, q10.y, a1);
        w = wx1 * wy0 * wz1; a0 = fmaf(w, q10.z, a0);   a1 = fmaf(w, q10.w, a1);
        w = wx1 * wy1 * wz0; a0 = fmaf(w, q11.x, a0);   a1 = fmaf(w, q11.y, a1);
        w = wx1 * wy1 * wz1; a0 = fmaf(w, q11.z, a0);   a1 = fmaf(w, q11.w, a1);
    } else {
        // ---- hashed path ----
        uint32_t hx0 = (uint32_t)cx;
        uint32_t hx1 = hx0 + 1u;
        uint32_t hy0 = (uint32_t)cy * P1;
        uint32_t hy1 = hy0 + P1;
        uint32_t hzb = (uint32_t)cz * P2;
        uint32_t hz0 = hzb        ^ (uint32_t)l;
        uint32_t hz1 = (hzb + P2) ^ (uint32_t)l;

        const float2* __restrict__ tbl = (const float2*)tables + ((size_t)l << 19);

        // combo j = dy*2 + dz; corner k: x0 -> k=j, x1 -> k=j+4
        uint32_t hj[4];
        hj[0] = hy0 ^ hz0;
        hj[1] = hy0 ^ hz1;
        hj[2] = hy1 ^ hz0;
        hj[3] = hy1 ^ hz1;

        float2 e[8];

        if ((cx & 1) == 0) {
            // cx even: idx(x+1) == idx(x) ^ 1 -> one aligned float4 per combo
            const float4* __restrict__ tbl4 = (const float4*)tbl;
#pragma unroll
            for (int j = 0; j < 4; ++j) {
                uint32_t i0 = (hx0 ^ hj[j]) & TABLE_MASK;
                float4 q = __ldg(tbl4 + (i0 >> 1));
                bool lo = (i0 & 1u) == 0u;
                e[j]     = lo ? make_float2(q.x, q.y) : make_float2(q.z, q.w);
                e[j + 4] = lo ? make_float2(q.z, q.w) : make_float2(q.x, q.y);
            }
        } else {
#pragma unroll
            for (int j = 0; j < 4; ++j) {
                e[j]     = __ldg(tbl + ((hx0 ^ hj[j]) & TABLE_MASK));
                e[j + 4] = __ldg(tbl + ((hx1 ^ hj[j]) & TABLE_MASK));
            }
        }

        // weights in reference corner order k = dx*4 + dy*2 + dz
        float w[8];
#pragma unroll
        for (int k = 0; k < 8; ++k) {
            w[k] = ((k & 4) ? wx1 : wx0)
                 * ((k & 2) ? wy1 : wy0)
                 * ((k & 1) ? wz1 : wz0);
        }
        a0 = 0.0f; a1 = 0.0f;
#pragma unroll
        for (int k = 0; k < 8; ++k) {
            a0 = fmaf(w[k], e[k].x, a0);
            a1 = fmaf(w[k], e[k].y, a1);
        }
    }

    float2* o = (float2*)(out + (size_t)n * (NUM_LEVELS * 2));
    o[l] = make_float2(a0, a1);
}

extern "C" void kernel_launch(void* const* d_in, const int* in_sizes, int n_in,
                              void* d_out, int out_size)
{
    const float* x      = (const float*)d_in[0];
    const float* tables = (const float*)d_in[1];
    float* out          = (float*)d_out;

    int N = in_sizes[0] / 3;

    build_dense_kernel<<<(D_TOTAL + 255) / 256, 256>>>(tables);

    int total = N * NUM_LEVELS;
    hash_encode_kernel<<<(total + 255) / 256, 256>>>(x, tables, out, N);
}